// round 1
// baseline (speedup 1.0000x reference)
#include <cuda_runtime.h>
#include <math.h>

#define BB 8
#define NN 4096
#define NQ1 2048
#define NQ2 2048
#define KTOT 64

// Scratch (allocation-free rule: __device__ globals)
__device__ float4 g_feats[(long)BB * NN * KTOT];        // [pt][slot] = (rx,ry,rz,dist)
__device__ float  g_grouped[(long)BB * NN * KTOT * 3];  // [pt][slot][3]
__device__ float  g_G[16];
__device__ float  g_u[4];
__device__ float  g_w[4];
__device__ float  g_c0;

// ---------------------------------------------------------------------------
// Precompute G = Wq Wk^T (4x4), u = Wq bk, w = Wk bq, c0 = bq.bk
// Wq/Wk are [4,64] row-major.
// ---------------------------------------------------------------------------
__global__ void precompute_kernel(const float* __restrict__ Wq,
                                  const float* __restrict__ Wk,
                                  const float* __restrict__ bq,
                                  const float* __restrict__ bk) {
    int t = threadIdx.x;
    if (t < 16) {
        int i = t >> 2, j = t & 3;
        float s = 0.f;
        for (int c = 0; c < 64; c++) s = fmaf(Wq[i * 64 + c], Wk[j * 64 + c], s);
        g_G[t] = s;
    } else if (t < 20) {
        int i = t - 16;
        float s = 0.f;
        for (int c = 0; c < 64; c++) s = fmaf(Wq[i * 64 + c], bk[c], s);
        g_u[i] = s;
    } else if (t < 24) {
        int j = t - 20;
        float s = 0.f;
        for (int c = 0; c < 64; c++) s = fmaf(Wk[j * 64 + c], bq[c], s);
        g_w[j] = s;
    } else if (t == 24) {
        float s = 0.f;
        for (int c = 0; c < 64; c++) s = fmaf(bq[c], bk[c], s);
        g_c0 = s;
    }
}

// ---------------------------------------------------------------------------
// Brute-force KNN: one thread per query, db tile in shared memory.
// db: [B,3,N] source for this knn type. Queries = concat(p1[ridx1], p2[ridx2]).
// Writes feats (resi,dist) and grouped (nn xyz) into scratch at slot_base.
// ---------------------------------------------------------------------------
template <int K>
__global__ __launch_bounds__(256) void knn_kernel(
    const float* __restrict__ db,
    const float* __restrict__ p1, const float* __restrict__ p2,
    const int* __restrict__ ridx1, const int* __restrict__ ridx2,
    int slot_base) {
    extern __shared__ float4 sdb[];  // NN entries, 64KB

    const int b = blockIdx.y;
    const float* dbx = db + (long)b * 3 * NN;
    for (int j = threadIdx.x; j < NN; j += blockDim.x) {
        sdb[j] = make_float4(dbx[j], dbx[NN + j], dbx[2 * NN + j], 0.f);
    }
    __syncthreads();

    const int qi = blockIdx.x * blockDim.x + threadIdx.x;

    float qx, qy, qz;
    if (qi < NQ1) {
        int idx = ridx1[b * NQ1 + qi];
        const float* s = p1 + (long)b * 3 * NN;
        qx = s[idx]; qy = s[NN + idx]; qz = s[2 * NN + idx];
    } else {
        int idx = ridx2[b * NQ2 + (qi - NQ1)];
        const float* s = p2 + (long)b * 3 * NN;
        qx = s[idx]; qy = s[NN + idx]; qz = s[2 * NN + idx];
    }

    float bestd[K];
    int   besti[K];
#pragma unroll
    for (int s = 0; s < K; s++) { bestd[s] = 3.4e38f; besti[s] = 0; }
    float worst = 3.4e38f;
    int   wp = 0;

    for (int j = 0; j < NN; j++) {
        float4 p = sdb[j];
        float dx = p.x - qx, dy = p.y - qy, dz = p.z - qz;
        float d2 = fmaf(dx, dx, fmaf(dy, dy, dz * dz));
        if (d2 < worst) {
            bestd[wp] = d2;
            besti[wp] = j;
            // rescan for new worst
            float w0 = bestd[0];
            int   p0 = 0;
#pragma unroll
            for (int s = 1; s < K; s++) {
                if (bestd[s] > w0) { w0 = bestd[s]; p0 = s; }
            }
            worst = w0;
            wp = p0;
        }
    }

    const long pt = (long)b * NN + qi;
    float4* fout = g_feats + pt * KTOT + slot_base;
    float*  gout = g_grouped + (pt * KTOT + slot_base) * 3;
#pragma unroll
    for (int s = 0; s < K; s++) {
        float4 p = sdb[besti[s]];
        float rx = p.x - qx, ry = p.y - qy, rz = p.z - qz;
        float sq = fmaf(rx, rx, fmaf(ry, ry, rz * rz));
        float dd = (sq > 0.f) ? sqrtf(sq) : 0.f;
        fout[s] = make_float4(rx, ry, rz, dd);
        gout[s * 3 + 0] = p.x;
        gout[s * 3 + 1] = p.y;
        gout[s * 3 + 2] = p.z;
    }
}

// ---------------------------------------------------------------------------
// Attention + weighted fusion. Rank-4 factorization:
//   logits_ij = (F_i G F_j^T + F_i.u + F_j.w + c0) * 0.125
//   AF = attn @ F  (64x4);  score_i = max_c (AF_i . Wv[:,c] + bv[c])
//   out = sum_i softmax(score)_i * grouped_i
// One 64-thread group per point, 4 points per 256-thread block.
// ---------------------------------------------------------------------------
__global__ __launch_bounds__(256) void attn_kernel(
    const float* __restrict__ Wv, const float* __restrict__ bv,
    float* __restrict__ out) {
    __shared__ float4 sF[4][64];
    __shared__ float  sB[4][64];     // F_j.w column terms, later reused for exp sums
    __shared__ float  sS[4][64];     // per-neighbor scores
    __shared__ float  sWv[4][64];    // Wv[d][c]
    __shared__ float  sbv[64];
    __shared__ float  sRed[4][2][3];

    const int tid = threadIdx.x;
    const int g = tid >> 6;
    const int t = tid & 63;

    sWv[g][t] = Wv[tid];             // 256 floats, direct map
    if (tid < 64) sbv[tid] = bv[tid];

    const long pt = (long)blockIdx.x * 4 + g;

    float4 F = g_feats[pt * KTOT + t];
    sF[g][t] = F;

    // P = F_row . G  (G row-major [i][j] over input-dim pairs)
    float P0 = F.x * g_G[0]  + F.y * g_G[4]  + F.z * g_G[8]  + F.w * g_G[12];
    float P1 = F.x * g_G[1]  + F.y * g_G[5]  + F.z * g_G[9]  + F.w * g_G[13];
    float P2 = F.x * g_G[2]  + F.y * g_G[6]  + F.z * g_G[10] + F.w * g_G[14];
    float P3 = F.x * g_G[3]  + F.y * g_G[7]  + F.z * g_G[11] + F.w * g_G[15];
    float a_t = F.x * g_u[0] + F.y * g_u[1] + F.z * g_u[2] + F.w * g_u[3] + g_c0;
    float b_t = F.x * g_w[0] + F.y * g_w[1] + F.z * g_w[2] + F.w * g_w[3];
    sB[g][t] = b_t;

    float gx = g_grouped[(pt * KTOT + t) * 3 + 0];
    float gy = g_grouped[(pt * KTOT + t) * 3 + 1];
    float gz = g_grouped[(pt * KTOT + t) * 3 + 2];

    __syncthreads();

    const float scale = 0.125f;  // 1/sqrt(64)

    // pass 1: row max
    float m = -3.4e38f;
#pragma unroll 8
    for (int j = 0; j < 64; j++) {
        float4 Fj = sF[g][j];
        float l = fmaf(P0, Fj.x, fmaf(P1, Fj.y, fmaf(P2, Fj.z, fmaf(P3, Fj.w, a_t + sB[g][j])))) * scale;
        m = fmaxf(m, l);
    }

    // pass 2: exp-sum and attn@F accumulation (unnormalized)
    float ssum = 0.f, a0 = 0.f, a1 = 0.f, a2 = 0.f, a3 = 0.f;
#pragma unroll 8
    for (int j = 0; j < 64; j++) {
        float4 Fj = sF[g][j];
        float l = fmaf(P0, Fj.x, fmaf(P1, Fj.y, fmaf(P2, Fj.z, fmaf(P3, Fj.w, a_t + sB[g][j])))) * scale;
        float e = __expf(l - m);
        ssum += e;
        a0 = fmaf(e, Fj.x, a0);
        a1 = fmaf(e, Fj.y, a1);
        a2 = fmaf(e, Fj.z, a2);
        a3 = fmaf(e, Fj.w, a3);
    }
    float inv = 1.f / ssum;
    a0 *= inv; a1 *= inv; a2 *= inv; a3 *= inv;

    // score = max over 64 output channels of AF . Wv[:,c] + bv[c]
    float sc = -3.4e38f;
#pragma unroll 8
    for (int c = 0; c < 64; c++) {
        float y = fmaf(a0, sWv[0][c], fmaf(a1, sWv[1][c], fmaf(a2, sWv[2][c], fmaf(a3, sWv[3][c], sbv[c]))));
        sc = fmaxf(sc, y);
    }
    sS[g][t] = sc;
    __syncthreads();

    // softmax over the 64 neighbors of this group
    float m2 = -3.4e38f;
#pragma unroll 8
    for (int j = 0; j < 64; j++) m2 = fmaxf(m2, sS[g][j]);
    float e_t = __expf(sc - m2);
    sB[g][t] = e_t;            // safe: everyone is past reading sB (sync above)
    __syncthreads();
    float sum2 = 0.f;
#pragma unroll 8
    for (int j = 0; j < 64; j++) sum2 += sB[g][j];
    float wgt = e_t / sum2;

    // weighted sum of grouped positions across 64 threads
    float cx = wgt * gx, cy = wgt * gy, cz = wgt * gz;
#pragma unroll
    for (int off = 16; off > 0; off >>= 1) {
        cx += __shfl_down_sync(0xffffffffu, cx, off);
        cy += __shfl_down_sync(0xffffffffu, cy, off);
        cz += __shfl_down_sync(0xffffffffu, cz, off);
    }
    const int wg = t >> 5;
    if ((t & 31) == 0) {
        sRed[g][wg][0] = cx; sRed[g][wg][1] = cy; sRed[g][wg][2] = cz;
    }
    __syncthreads();
    if (t == 0) {
        int b = (int)(pt / NN);
        int n = (int)(pt % NN);
        float ox = sRed[g][0][0] + sRed[g][1][0];
        float oy = sRed[g][0][1] + sRed[g][1][1];
        float oz = sRed[g][0][2] + sRed[g][1][2];
        out[(long)b * 3 * NN + 0 * NN + n] = ox;
        out[(long)b * 3 * NN + 1 * NN + n] = oy;
        out[(long)b * 3 * NN + 2 * NN + n] = oz;
    }
}

// ---------------------------------------------------------------------------
extern "C" void kernel_launch(void* const* d_in, const int* in_sizes, int n_in,
                              void* d_out, int out_size) {
    const float* points1 = (const float*)d_in[0];
    const float* points2 = (const float*)d_in[1];
    const float* pc      = (const float*)d_in[2];
    const float* Wq      = (const float*)d_in[3];
    const float* Wk      = (const float*)d_in[4];
    const float* Wv      = (const float*)d_in[5];
    const float* bq      = (const float*)d_in[6];
    const float* bk      = (const float*)d_in[7];
    const float* bv      = (const float*)d_in[8];
    const int*   ridx1   = (const int*)d_in[9];
    const int*   ridx2   = (const int*)d_in[10];
    float* out = (float*)d_out;

    const size_t smem = (size_t)NN * sizeof(float4);  // 64KB
    cudaFuncSetAttribute(knn_kernel<16>, cudaFuncAttributeMaxDynamicSharedMemorySize, (int)smem);
    cudaFuncSetAttribute(knn_kernel<32>, cudaFuncAttributeMaxDynamicSharedMemorySize, (int)smem);

    precompute_kernel<<<1, 64>>>(Wq, Wk, bq, bk);

    dim3 grid(NN / 256, BB);
    knn_kernel<16><<<grid, 256, smem>>>(points1, points1, points2, ridx1, ridx2, 0);
    knn_kernel<16><<<grid, 256, smem>>>(points2, points1, points2, ridx1, ridx2, 16);
    knn_kernel<32><<<grid, 256, smem>>>(pc,      points1, points2, ridx1, ridx2, 32);

    attn_kernel<<<(BB * NN) / 4, 256>>>(Wv, bv, out);
}

// round 2
// speedup vs baseline: 2.1506x; 2.1506x over previous
#include <cuda_runtime.h>
#include <math.h>

#define BB 8
#define NN 4096
#define NQ1 2048
#define NQ2 2048
#define KTOT 64
#define FINF 3.4e38f

// Scratch (allocation-free rule: __device__ globals)
__device__ float4 g_feats[(long)BB * NN * KTOT];        // [pt][slot] = (rx,ry,rz,dist)
__device__ float  g_grouped[(long)BB * NN * KTOT * 3];  // [pt][slot][3]
__device__ float  g_G[16];
__device__ float  g_u[4];
__device__ float  g_w[4];
__device__ float  g_c0;

// ---------------------------------------------------------------------------
// Precompute G = Wq Wk^T (4x4), u = Wq bk, w = Wk bq, c0 = bq.bk
// ---------------------------------------------------------------------------
__global__ void precompute_kernel(const float* __restrict__ Wq,
                                  const float* __restrict__ Wk,
                                  const float* __restrict__ bq,
                                  const float* __restrict__ bk) {
    int t = threadIdx.x;
    if (t < 16) {
        int i = t >> 2, j = t & 3;
        float s = 0.f;
        for (int c = 0; c < 64; c++) s = fmaf(Wq[i * 64 + c], Wk[j * 64 + c], s);
        g_G[t] = s;
    } else if (t < 20) {
        int i = t - 16;
        float s = 0.f;
        for (int c = 0; c < 64; c++) s = fmaf(Wq[i * 64 + c], bk[c], s);
        g_u[i] = s;
    } else if (t < 24) {
        int j = t - 20;
        float s = 0.f;
        for (int c = 0; c < 64; c++) s = fmaf(Wk[j * 64 + c], bq[c], s);
        g_w[j] = s;
    } else if (t == 24) {
        float s = 0.f;
        for (int c = 0; c < 64; c++) s = fmaf(bq[c], bk[c], s);
        g_c0 = s;
    }
}

// ---------------------------------------------------------------------------
// Warp-wide bitonic sort of 64 (score,idx) pairs, 2 per lane.
// Element index e = r*32 + lane. Ascending by score over e after completion.
// ---------------------------------------------------------------------------
__device__ __forceinline__ void sort64(float& s0, int& i0, float& s1, int& i1,
                                       int lane) {
#pragma unroll
    for (int k = 2; k <= 64; k <<= 1) {
#pragma unroll
        for (int j = k >> 1; j > 0; j >>= 1) {
            if (j == 32) {
                // within-thread exchange (only occurs for k=64, ascending)
                bool sw = (s1 < s0);
                float ts = sw ? s1 : s0;
                int ti = sw ? i1 : i0;
                s1 = sw ? s0 : s1;
                i1 = sw ? i0 : i1;
                s0 = ts;
                i0 = ti;
            } else {
                bool lower = (lane & j) == 0;
                {
                    float os = __shfl_xor_sync(0xffffffffu, s0, j);
                    int oi = __shfl_xor_sync(0xffffffffu, i0, j);
                    bool takeMin = (lower == ((lane & k) == 0));
                    bool to = takeMin ? (os < s0) : (os > s0);
                    if (to) { s0 = os; i0 = oi; }
                }
                {
                    float os = __shfl_xor_sync(0xffffffffu, s1, j);
                    int oi = __shfl_xor_sync(0xffffffffu, i1, j);
                    bool takeMin = (lower == (((lane + 32) & k) == 0));
                    bool to = takeMin ? (os < s1) : (os > s1);
                    if (to) { s1 = os; i1 = oi; }
                }
            }
        }
    }
}

// Flush: merge kept-K (in s0 regs, lanes>=K hold INF for K<32) with pending
// candidates in smem buffer slots [K, count). After: s0 holds kept-K
// (lanes < K), threshold = K-th best, count = K.
template <int K>
__device__ __forceinline__ void knn_flush(uint2* buf, int lane, float& s0,
                                          int& i0, int& count, float& thr) {
    __syncwarp();
    int nNew = count - K;
    float s1 = FINF;
    int i1 = 0;
    if (lane < nNew) {
        uint2 e = buf[K + lane];
        s1 = __uint_as_float(e.x);
        i1 = (int)e.y;
    }
    sort64(s0, i0, s1, i1, lane);
    if (K < 32 && lane >= K) s0 = FINF;  // discard ranks >= K
    thr = __shfl_sync(0xffffffffu, s0, K - 1);
    count = K;
}

// ---------------------------------------------------------------------------
// Warp-per-query brute-force KNN with ballot-compacted candidate buffer.
// ---------------------------------------------------------------------------
template <int K>
__global__ __launch_bounds__(256) void knn_kernel(
    const float* __restrict__ db,
    const float* __restrict__ p1, const float* __restrict__ p2,
    const int* __restrict__ ridx1, const int* __restrict__ ridx2,
    int slot_base) {
    extern __shared__ float4 sdb[];       // NN entries, 64KB (w = 0.5*|p|^2)
    __shared__ uint2 scand[8][64];        // per-warp candidate buffer

    const int b = blockIdx.y;
    const float* dbx = db + (long)b * 3 * NN;
    for (int j = threadIdx.x; j < NN; j += 256) {
        float x = dbx[j], y = dbx[NN + j], z = dbx[2 * NN + j];
        sdb[j] = make_float4(x, y, z, 0.5f * fmaf(x, x, fmaf(y, y, z * z)));
    }
    __syncthreads();

    const int w = threadIdx.x >> 5;
    const int lane = threadIdx.x & 31;
    const int qi = blockIdx.x * 8 + w;     // 0..4095 within batch

    float qx, qy, qz;
    if (qi < NQ1) {
        int idx = ridx1[b * NQ1 + qi];
        const float* s = p1 + (long)b * 3 * NN;
        qx = s[idx]; qy = s[NN + idx]; qz = s[2 * NN + idx];
    } else {
        int idx = ridx2[b * NQ2 + (qi - NQ1)];
        const float* s = p2 + (long)b * 3 * NN;
        qx = s[idx]; qy = s[NN + idx]; qz = s[2 * NN + idx];
    }
    const float qnx = -qx, qny = -qy, qnz = -qz;

    float s0 = FINF;
    int i0 = 0;
    float thr = FINF;
    int count = K;                         // virtual kept region occupies [0,K)
    uint2* buf = scand[w];
    const unsigned lt = (1u << lane) - 1u;
    constexpr int CAP = K + 32;

    for (int j0 = 0; j0 < NN; j0 += 32) {
        float4 p = sdb[j0 + lane];
        // score = 0.5|p|^2 - q.p  (monotonic in d2; same expansion as reference)
        float sc = fmaf(qnx, p.x, fmaf(qny, p.y, fmaf(qnz, p.z, p.w)));
        bool pred = sc < thr;
        unsigned mask = __ballot_sync(0xffffffffu, pred);
        int n = __popc(mask);
        if (count + n > CAP) {             // uniform branch
            knn_flush<K>(buf, lane, s0, i0, count, thr);
            pred = pred && (sc < thr);
            mask = __ballot_sync(0xffffffffu, pred);
            n = __popc(mask);
        }
        if (pred) {
            int pos = count + __popc(mask & lt);
            buf[pos] = make_uint2(__float_as_uint(sc), (unsigned)(j0 + lane));
        }
        count += n;
    }
    knn_flush<K>(buf, lane, s0, i0, count, thr);

    // Writeout: lane l holds the (l+1)-th nearest (order irrelevant downstream).
    if (K == 32 || lane < K) {
        float4 p = sdb[i0];
        float rx = p.x - qx, ry = p.y - qy, rz = p.z - qz;
        float sq = fmaf(rx, rx, fmaf(ry, ry, rz * rz));
        float dd = (sq > 0.f) ? sqrtf(sq) : 0.f;
        const long pt = (long)b * NN + qi;
        g_feats[pt * KTOT + slot_base + lane] = make_float4(rx, ry, rz, dd);
        float* go = g_grouped + (pt * KTOT + slot_base + lane) * 3;
        go[0] = p.x;
        go[1] = p.y;
        go[2] = p.z;
    }
}

// ---------------------------------------------------------------------------
// Attention + weighted fusion (rank-4 factorization). Unchanged from R1.
// ---------------------------------------------------------------------------
__global__ __launch_bounds__(256) void attn_kernel(
    const float* __restrict__ Wv, const float* __restrict__ bv,
    float* __restrict__ out) {
    __shared__ float4 sF[4][64];
    __shared__ float  sB[4][64];
    __shared__ float  sS[4][64];
    __shared__ float  sWv[4][64];
    __shared__ float  sbv[64];
    __shared__ float  sRed[4][2][3];

    const int tid = threadIdx.x;
    const int g = tid >> 6;
    const int t = tid & 63;

    sWv[g][t] = Wv[tid];
    if (tid < 64) sbv[tid] = bv[tid];

    const long pt = (long)blockIdx.x * 4 + g;

    float4 F = g_feats[pt * KTOT + t];
    sF[g][t] = F;

    float P0 = F.x * g_G[0]  + F.y * g_G[4]  + F.z * g_G[8]  + F.w * g_G[12];
    float P1 = F.x * g_G[1]  + F.y * g_G[5]  + F.z * g_G[9]  + F.w * g_G[13];
    float P2 = F.x * g_G[2]  + F.y * g_G[6]  + F.z * g_G[10] + F.w * g_G[14];
    float P3 = F.x * g_G[3]  + F.y * g_G[7]  + F.z * g_G[11] + F.w * g_G[15];
    float a_t = F.x * g_u[0] + F.y * g_u[1] + F.z * g_u[2] + F.w * g_u[3] + g_c0;
    float b_t = F.x * g_w[0] + F.y * g_w[1] + F.z * g_w[2] + F.w * g_w[3];
    sB[g][t] = b_t;

    float gx = g_grouped[(pt * KTOT + t) * 3 + 0];
    float gy = g_grouped[(pt * KTOT + t) * 3 + 1];
    float gz = g_grouped[(pt * KTOT + t) * 3 + 2];

    __syncthreads();

    const float scale = 0.125f;

    float m = -FINF;
#pragma unroll 8
    for (int j = 0; j < 64; j++) {
        float4 Fj = sF[g][j];
        float l = fmaf(P0, Fj.x, fmaf(P1, Fj.y, fmaf(P2, Fj.z, fmaf(P3, Fj.w, a_t + sB[g][j])))) * scale;
        m = fmaxf(m, l);
    }

    float ssum = 0.f, a0 = 0.f, a1 = 0.f, a2 = 0.f, a3 = 0.f;
#pragma unroll 8
    for (int j = 0; j < 64; j++) {
        float4 Fj = sF[g][j];
        float l = fmaf(P0, Fj.x, fmaf(P1, Fj.y, fmaf(P2, Fj.z, fmaf(P3, Fj.w, a_t + sB[g][j])))) * scale;
        float e = __expf(l - m);
        ssum += e;
        a0 = fmaf(e, Fj.x, a0);
        a1 = fmaf(e, Fj.y, a1);
        a2 = fmaf(e, Fj.z, a2);
        a3 = fmaf(e, Fj.w, a3);
    }
    float inv = 1.f / ssum;
    a0 *= inv; a1 *= inv; a2 *= inv; a3 *= inv;

    float sc = -FINF;
#pragma unroll 8
    for (int c = 0; c < 64; c++) {
        float y = fmaf(a0, sWv[0][c], fmaf(a1, sWv[1][c], fmaf(a2, sWv[2][c], fmaf(a3, sWv[3][c], sbv[c]))));
        sc = fmaxf(sc, y);
    }
    sS[g][t] = sc;
    __syncthreads();

    float m2 = -FINF;
#pragma unroll 8
    for (int j = 0; j < 64; j++) m2 = fmaxf(m2, sS[g][j]);
    float e_t = __expf(sc - m2);
    sB[g][t] = e_t;
    __syncthreads();
    float sum2 = 0.f;
#pragma unroll 8
    for (int j = 0; j < 64; j++) sum2 += sB[g][j];
    float wgt = e_t / sum2;

    float cx = wgt * gx, cy = wgt * gy, cz = wgt * gz;
#pragma unroll
    for (int off = 16; off > 0; off >>= 1) {
        cx += __shfl_down_sync(0xffffffffu, cx, off);
        cy += __shfl_down_sync(0xffffffffu, cy, off);
        cz += __shfl_down_sync(0xffffffffu, cz, off);
    }
    const int wg = t >> 5;
    if ((t & 31) == 0) {
        sRed[g][wg][0] = cx; sRed[g][wg][1] = cy; sRed[g][wg][2] = cz;
    }
    __syncthreads();
    if (t == 0) {
        int b = (int)(pt / NN);
        int n = (int)(pt % NN);
        out[(long)b * 3 * NN + 0 * NN + n] = sRed[g][0][0] + sRed[g][1][0];
        out[(long)b * 3 * NN + 1 * NN + n] = sRed[g][0][1] + sRed[g][1][1];
        out[(long)b * 3 * NN + 2 * NN + n] = sRed[g][0][2] + sRed[g][1][2];
    }
}

// ---------------------------------------------------------------------------
extern "C" void kernel_launch(void* const* d_in, const int* in_sizes, int n_in,
                              void* d_out, int out_size) {
    const float* points1 = (const float*)d_in[0];
    const float* points2 = (const float*)d_in[1];
    const float* pc      = (const float*)d_in[2];
    const float* Wq      = (const float*)d_in[3];
    const float* Wk      = (const float*)d_in[4];
    const float* Wv      = (const float*)d_in[5];
    const float* bq      = (const float*)d_in[6];
    const float* bk      = (const float*)d_in[7];
    const float* bv      = (const float*)d_in[8];
    const int*   ridx1   = (const int*)d_in[9];
    const int*   ridx2   = (const int*)d_in[10];
    float* out = (float*)d_out;

    const size_t smem = (size_t)NN * sizeof(float4);  // 64KB dynamic
    cudaFuncSetAttribute(knn_kernel<16>, cudaFuncAttributeMaxDynamicSharedMemorySize, (int)smem);
    cudaFuncSetAttribute(knn_kernel<32>, cudaFuncAttributeMaxDynamicSharedMemorySize, (int)smem);

    precompute_kernel<<<1, 64>>>(Wq, Wk, bq, bk);

    dim3 grid(NN / 8, BB);  // 512 x 8 = 4096 blocks, warp per query
    knn_kernel<16><<<grid, 256, smem>>>(points1, points1, points2, ridx1, ridx2, 0);
    knn_kernel<16><<<grid, 256, smem>>>(points2, points1, points2, ridx1, ridx2, 16);
    knn_kernel<32><<<grid, 256, smem>>>(pc,      points1, points2, ridx1, ridx2, 32);

    attn_kernel<<<(BB * NN) / 4, 256>>>(Wv, bv, out);
}

// round 3
// speedup vs baseline: 3.1924x; 1.4845x over previous
#include <cuda_runtime.h>
#include <math.h>

#define BB 8
#define NN 4096
#define NQ1 2048
#define NQ2 2048
#define KTOT 64
#define FINF 3.4e38f

// Scratch (allocation-free rule: __device__ globals)
__device__ float4 g_feats[(long)BB * NN * KTOT];        // [pt][slot] = (rx,ry,rz,dist)
__device__ float  g_grouped[(long)BB * NN * KTOT * 3];  // [pt][slot][3]
__device__ float  g_G[16];
__device__ float  g_u[4];
__device__ float  g_w[4];
__device__ float  g_c0;

// ---------------------------------------------------------------------------
// Precompute G = Wq Wk^T (4x4), u = Wq bk, w = Wk bq, c0 = bq.bk
// ---------------------------------------------------------------------------
__global__ void precompute_kernel(const float* __restrict__ Wq,
                                  const float* __restrict__ Wk,
                                  const float* __restrict__ bq,
                                  const float* __restrict__ bk) {
    int t = threadIdx.x;
    if (t < 16) {
        int i = t >> 2, j = t & 3;
        float s = 0.f;
        for (int c = 0; c < 64; c++) s = fmaf(Wq[i * 64 + c], Wk[j * 64 + c], s);
        g_G[t] = s;
    } else if (t < 20) {
        int i = t - 16;
        float s = 0.f;
        for (int c = 0; c < 64; c++) s = fmaf(Wq[i * 64 + c], bk[c], s);
        g_u[i] = s;
    } else if (t < 24) {
        int j = t - 20;
        float s = 0.f;
        for (int c = 0; c < 64; c++) s = fmaf(Wk[j * 64 + c], bq[c], s);
        g_w[j] = s;
    } else if (t == 24) {
        float s = 0.f;
        for (int c = 0; c < 64; c++) s = fmaf(bq[c], bk[c], s);
        g_c0 = s;
    }
}

// ---------------------------------------------------------------------------
// Warp sorting primitives: one (score,idx) element per lane.
// ---------------------------------------------------------------------------
__device__ __forceinline__ void cex_stage(float& s, int& i, int lane, int j,
                                          bool asc_block) {
    float os = __shfl_xor_sync(0xffffffffu, s, j);
    int oi = __shfl_xor_sync(0xffffffffu, i, j);
    bool lower = (lane & j) == 0;
    bool takeMin = (lower == asc_block);
    bool take = takeMin ? (os < s) : (os > s);
    if (take) { s = os; i = oi; }
}

// Full ascending bitonic sort of 32 elements across lanes.
__device__ __forceinline__ void sort32(float& s, int& i, int lane) {
#pragma unroll
    for (int k = 2; k <= 32; k <<= 1) {
#pragma unroll
        for (int j = k >> 1; j > 0; j >>= 1) {
            cex_stage(s, i, lane, j, (lane & k) == 0 || k == 32);
        }
    }
}

// Clean a bitonic sequence of 32 into ascending order.
__device__ __forceinline__ void clean32(float& s, int& i, int lane) {
#pragma unroll
    for (int j = 16; j > 0; j >>= 1) cex_stage(s, i, lane, j, true);
}

// Flush: merge sorted kept list (s0,i0 ascending over lanes) with `pend`
// unsorted candidates in buf[0..pend). Result: s0 = smallest 32 of the union,
// sorted ascending; thr = K-th smallest; pend = 0.
template <int K>
__device__ __forceinline__ void knn_flush(uint2* buf, int lane, float& s0,
                                          int& i0, int& pend, float& thr) {
    __syncwarp();
    float s1 = FINF;
    int i1 = 0;
    if (lane < pend) {
        uint2 e = buf[lane];
        s1 = __uint_as_float(e.x);
        i1 = (int)e.y;
    }
    sort32(s1, i1, lane);
    // bitonic merge lower half: L[i] = min(kept[i], cand[31-i])
    float os = __shfl_sync(0xffffffffu, s1, 31 - lane);
    int oi = __shfl_sync(0xffffffffu, i1, 31 - lane);
    if (os < s0) { s0 = os; i0 = oi; }
    clean32(s0, i0, lane);
    thr = __shfl_sync(0xffffffffu, s0, K - 1);
    pend = 0;
}

// ---------------------------------------------------------------------------
// Warp-per-query brute-force KNN. 512 threads/block, 16 queries/block.
// ---------------------------------------------------------------------------
template <int K>
__global__ __launch_bounds__(512, 3) void knn_kernel(
    const float* __restrict__ db,
    const float* __restrict__ p1, const float* __restrict__ p2,
    const int* __restrict__ ridx1, const int* __restrict__ ridx2,
    int slot_base) {
    extern __shared__ float4 sdb[];       // NN entries, 64KB (w = 0.5*|p|^2)
    __shared__ uint2 scand[16][32];       // per-warp pending-candidate buffer

    const int b = blockIdx.y;
    const float* dbx = db + (long)b * 3 * NN;
    for (int j = threadIdx.x; j < NN; j += 512) {
        float x = dbx[j], y = dbx[NN + j], z = dbx[2 * NN + j];
        sdb[j] = make_float4(x, y, z, 0.5f * fmaf(x, x, fmaf(y, y, z * z)));
    }
    __syncthreads();

    const int w = threadIdx.x >> 5;
    const int lane = threadIdx.x & 31;
    const int qi = blockIdx.x * 16 + w;    // 0..4095 within batch

    float qx, qy, qz;
    if (qi < NQ1) {
        int idx = ridx1[b * NQ1 + qi];
        const float* s = p1 + (long)b * 3 * NN;
        qx = s[idx]; qy = s[NN + idx]; qz = s[2 * NN + idx];
    } else {
        int idx = ridx2[b * NQ2 + (qi - NQ1)];
        const float* s = p2 + (long)b * 3 * NN;
        qx = s[idx]; qy = s[NN + idx]; qz = s[2 * NN + idx];
    }
    const float qnx = -qx, qny = -qy, qnz = -qz;

    uint2* buf = scand[w];
    const unsigned lt = (1u << lane) - 1u;

    // Seed: kept = sorted scores of the first 32 db points; exact K-th-best thr.
    float s0;
    int i0 = lane;
    {
        float4 p = sdb[lane];
        s0 = fmaf(qnx, p.x, fmaf(qny, p.y, fmaf(qnz, p.z, p.w)));
        sort32(s0, i0, lane);
    }
    float thr = __shfl_sync(0xffffffffu, s0, K - 1);
    int pend = 0;

    for (int j0 = 32; j0 < NN; j0 += 32) {
        float4 p = sdb[j0 + lane];
        // score = 0.5|p|^2 - q.p  (monotonic in squared distance)
        float sc = fmaf(qnx, p.x, fmaf(qny, p.y, fmaf(qnz, p.z, p.w)));
        unsigned mask = __ballot_sync(0xffffffffu, sc < thr);
        if (mask) {                         // warp-uniform
            int n = __popc(mask);
            if (pend + n > 32) {
                knn_flush<K>(buf, lane, s0, i0, pend, thr);
                mask = __ballot_sync(0xffffffffu, sc < thr);
                n = __popc(mask);
            }
            if (sc < thr) {
                buf[pend + __popc(mask & lt)] =
                    make_uint2(__float_as_uint(sc), (unsigned)(j0 + lane));
            }
            pend += n;
        }
    }
    if (pend) knn_flush<K>(buf, lane, s0, i0, pend, thr);

    // Writeout: lane l holds the (l+1)-th nearest; order irrelevant downstream.
    if (K == 32 || lane < K) {
        float4 p = sdb[i0];
        float rx = p.x - qx, ry = p.y - qy, rz = p.z - qz;
        float sq = fmaf(rx, rx, fmaf(ry, ry, rz * rz));
        float dd = (sq > 0.f) ? sqrtf(sq) : 0.f;
        const long pt = (long)b * NN + qi;
        g_feats[pt * KTOT + slot_base + lane] = make_float4(rx, ry, rz, dd);
        float* go = g_grouped + (pt * KTOT + slot_base + lane) * 3;
        go[0] = p.x;
        go[1] = p.y;
        go[2] = p.z;
    }
}

// ---------------------------------------------------------------------------
// Attention + weighted fusion (rank-4 factorization).
// ---------------------------------------------------------------------------
__global__ __launch_bounds__(256) void attn_kernel(
    const float* __restrict__ Wv, const float* __restrict__ bv,
    float* __restrict__ out) {
    __shared__ float4 sF[4][64];
    __shared__ float  sB[4][64];
    __shared__ float  sS[4][64];
    __shared__ float  sWv[4][64];
    __shared__ float  sbv[64];
    __shared__ float  sRed[4][2][3];

    const int tid = threadIdx.x;
    const int g = tid >> 6;
    const int t = tid & 63;

    sWv[g][t] = Wv[tid];
    if (tid < 64) sbv[tid] = bv[tid];

    const long pt = (long)blockIdx.x * 4 + g;

    float4 F = g_feats[pt * KTOT + t];
    sF[g][t] = F;

    float P0 = F.x * g_G[0]  + F.y * g_G[4]  + F.z * g_G[8]  + F.w * g_G[12];
    float P1 = F.x * g_G[1]  + F.y * g_G[5]  + F.z * g_G[9]  + F.w * g_G[13];
    float P2 = F.x * g_G[2]  + F.y * g_G[6]  + F.z * g_G[10] + F.w * g_G[14];
    float P3 = F.x * g_G[3]  + F.y * g_G[7]  + F.z * g_G[11] + F.w * g_G[15];
    float a_t = F.x * g_u[0] + F.y * g_u[1] + F.z * g_u[2] + F.w * g_u[3] + g_c0;
    float b_t = F.x * g_w[0] + F.y * g_w[1] + F.z * g_w[2] + F.w * g_w[3];
    sB[g][t] = b_t;

    float gx = g_grouped[(pt * KTOT + t) * 3 + 0];
    float gy = g_grouped[(pt * KTOT + t) * 3 + 1];
    float gz = g_grouped[(pt * KTOT + t) * 3 + 2];

    __syncthreads();

    const float scale = 0.125f;

    float m = -FINF;
#pragma unroll 8
    for (int j = 0; j < 64; j++) {
        float4 Fj = sF[g][j];
        float l = fmaf(P0, Fj.x, fmaf(P1, Fj.y, fmaf(P2, Fj.z, fmaf(P3, Fj.w, a_t + sB[g][j])))) * scale;
        m = fmaxf(m, l);
    }

    float ssum = 0.f, a0 = 0.f, a1 = 0.f, a2 = 0.f, a3 = 0.f;
#pragma unroll 8
    for (int j = 0; j < 64; j++) {
        float4 Fj = sF[g][j];
        float l = fmaf(P0, Fj.x, fmaf(P1, Fj.y, fmaf(P2, Fj.z, fmaf(P3, Fj.w, a_t + sB[g][j])))) * scale;
        float e = __expf(l - m);
        ssum += e;
        a0 = fmaf(e, Fj.x, a0);
        a1 = fmaf(e, Fj.y, a1);
        a2 = fmaf(e, Fj.z, a2);
        a3 = fmaf(e, Fj.w, a3);
    }
    float inv = 1.f / ssum;
    a0 *= inv; a1 *= inv; a2 *= inv; a3 *= inv;

    float sc = -FINF;
#pragma unroll 8
    for (int c = 0; c < 64; c++) {
        float y = fmaf(a0, sWv[0][c], fmaf(a1, sWv[1][c], fmaf(a2, sWv[2][c], fmaf(a3, sWv[3][c], sbv[c]))));
        sc = fmaxf(sc, y);
    }
    sS[g][t] = sc;
    __syncthreads();

    float m2 = -FINF;
#pragma unroll 8
    for (int j = 0; j < 64; j++) m2 = fmaxf(m2, sS[g][j]);
    float e_t = __expf(sc - m2);
    sB[g][t] = e_t;
    __syncthreads();
    float sum2 = 0.f;
#pragma unroll 8
    for (int j = 0; j < 64; j++) sum2 += sB[g][j];
    float wgt = e_t / sum2;

    float cx = wgt * gx, cy = wgt * gy, cz = wgt * gz;
#pragma unroll
    for (int off = 16; off > 0; off >>= 1) {
        cx += __shfl_down_sync(0xffffffffu, cx, off);
        cy += __shfl_down_sync(0xffffffffu, cy, off);
        cz += __shfl_down_sync(0xffffffffu, cz, off);
    }
    const int wg = t >> 5;
    if ((t & 31) == 0) {
        sRed[g][wg][0] = cx; sRed[g][wg][1] = cy; sRed[g][wg][2] = cz;
    }
    __syncthreads();
    if (t == 0) {
        int b = (int)(pt / NN);
        int n = (int)(pt % NN);
        out[(long)b * 3 * NN + 0 * NN + n] = sRed[g][0][0] + sRed[g][1][0];
        out[(long)b * 3 * NN + 1 * NN + n] = sRed[g][0][1] + sRed[g][1][1];
        out[(long)b * 3 * NN + 2 * NN + n] = sRed[g][0][2] + sRed[g][1][2];
    }
}

// ---------------------------------------------------------------------------
extern "C" void kernel_launch(void* const* d_in, const int* in_sizes, int n_in,
                              void* d_out, int out_size) {
    const float* points1 = (const float*)d_in[0];
    const float* points2 = (const float*)d_in[1];
    const float* pc      = (const float*)d_in[2];
    const float* Wq      = (const float*)d_in[3];
    const float* Wk      = (const float*)d_in[4];
    const float* Wv      = (const float*)d_in[5];
    const float* bq      = (const float*)d_in[6];
    const float* bk      = (const float*)d_in[7];
    const float* bv      = (const float*)d_in[8];
    const int*   ridx1   = (const int*)d_in[9];
    const int*   ridx2   = (const int*)d_in[10];
    float* out = (float*)d_out;

    const size_t smem = (size_t)NN * sizeof(float4);  // 64KB dynamic
    cudaFuncSetAttribute(knn_kernel<16>, cudaFuncAttributeMaxDynamicSharedMemorySize, (int)smem);
    cudaFuncSetAttribute(knn_kernel<32>, cudaFuncAttributeMaxDynamicSharedMemorySize, (int)smem);

    precompute_kernel<<<1, 64>>>(Wq, Wk, bq, bk);

    dim3 grid(NN / 16, BB);  // 256 x 8 blocks, 16 warps/block, warp per query
    knn_kernel<16><<<grid, 512, smem>>>(points1, points1, points2, ridx1, ridx2, 0);
    knn_kernel<16><<<grid, 512, smem>>>(points2, points1, points2, ridx1, ridx2, 16);
    knn_kernel<32><<<grid, 512, smem>>>(pc,      points1, points2, ridx1, ridx2, 32);

    attn_kernel<<<(BB * NN) / 4, 256>>>(Wv, bv, out);
}

// round 5
// speedup vs baseline: 3.3580x; 1.0519x over previous
#include <cuda_runtime.h>
#include <math.h>

#define BB 8
#define NN 4096
#define NQ1 2048
#define NQ2 2048
#define KTOT 64
#define FINF 3.4e38f

// Scratch (allocation-free rule: __device__ globals)
__device__ float4 g_feats[(long)BB * NN * KTOT];        // [pt][slot] = (rx,ry,rz,dist)
__device__ float  g_grouped[(long)BB * NN * KTOT * 3];  // [pt][slot][3]
__device__ float  g_G[16];
__device__ float  g_u[4];
__device__ float  g_w[4];
__device__ float  g_c0;

// ---------------------------------------------------------------------------
// Precompute G = Wq Wk^T (4x4), u = Wq bk, w = Wk bq, c0 = bq.bk
// ---------------------------------------------------------------------------
__global__ void precompute_kernel(const float* __restrict__ Wq,
                                  const float* __restrict__ Wk,
                                  const float* __restrict__ bq,
                                  const float* __restrict__ bk) {
    int t = threadIdx.x;
    if (t < 16) {
        int i = t >> 2, j = t & 3;
        float s = 0.f;
        for (int c = 0; c < 64; c++) s = fmaf(Wq[i * 64 + c], Wk[j * 64 + c], s);
        g_G[t] = s;
    } else if (t < 20) {
        int i = t - 16;
        float s = 0.f;
        for (int c = 0; c < 64; c++) s = fmaf(Wq[i * 64 + c], bk[c], s);
        g_u[i] = s;
    } else if (t < 24) {
        int j = t - 20;
        float s = 0.f;
        for (int c = 0; c < 64; c++) s = fmaf(Wk[j * 64 + c], bq[c], s);
        g_w[j] = s;
    } else if (t == 24) {
        float s = 0.f;
        for (int c = 0; c < 64; c++) s = fmaf(bq[c], bk[c], s);
        g_c0 = s;
    }
}

// ---------------------------------------------------------------------------
// Warp sorting primitives: one (score,idx) element per lane.
// ---------------------------------------------------------------------------
__device__ __forceinline__ void cex_stage(float& s, int& i, int lane, int j,
                                          bool asc_block) {
    float os = __shfl_xor_sync(0xffffffffu, s, j);
    int oi = __shfl_xor_sync(0xffffffffu, i, j);
    bool lower = (lane & j) == 0;
    bool takeMin = (lower == asc_block);
    bool take = takeMin ? (os < s) : (os > s);
    if (take) { s = os; i = oi; }
}

// Full ascending bitonic sort of 32 elements across lanes.
__device__ __forceinline__ void sort32(float& s, int& i, int lane) {
#pragma unroll
    for (int k = 2; k <= 32; k <<= 1) {
#pragma unroll
        for (int j = k >> 1; j > 0; j >>= 1) {
            cex_stage(s, i, lane, j, (lane & k) == 0 || k == 32);
        }
    }
}

// Clean a bitonic sequence of 32 into ascending order.
__device__ __forceinline__ void clean32(float& s, int& i, int lane) {
#pragma unroll
    for (int j = 16; j > 0; j >>= 1) cex_stage(s, i, lane, j, true);
}

// Flush: merge sorted kept list (s0,i0 ascending over lanes; top-32 so far)
// with `pend` unsorted candidates in buf[0..pend). Result: s0 = smallest 32
// of the union, sorted ascending; thr = K-th smallest; pend = 0.
// Correct for any K<=32: positions [0,K) are always the exact top-K.
__device__ __forceinline__ void knn_flush(uint2* buf, int lane, float& s0,
                                          int& i0, int& pend, float& thr,
                                          int K) {
    __syncwarp();
    float s1 = FINF;
    int i1 = 0;
    if (lane < pend) {
        uint2 e = buf[lane];
        s1 = __uint_as_float(e.x);
        i1 = (int)e.y;
    }
    sort32(s1, i1, lane);
    // bitonic merge lower half: L[i] = min(kept[i], cand[31-i])
    float os = __shfl_sync(0xffffffffu, s1, 31 - lane);
    int oi = __shfl_sync(0xffffffffu, i1, 31 - lane);
    if (os < s0) { s0 = os; i0 = oi; }
    clean32(s0, i0, lane);
    thr = __shfl_sync(0xffffffffu, s0, K - 1);
    pend = 0;
}

// ---------------------------------------------------------------------------
// Fused brute-force KNN: grid.z selects (db, K, slot). 4 queries per warp:
// one LDS.128 per 32-point batch serves 4 queries (smem traffic / 4).
// ---------------------------------------------------------------------------
__global__ __launch_bounds__(512, 2) void knn_kernel(
    const float* __restrict__ p1, const float* __restrict__ p2,
    const float* __restrict__ pc,
    const int* __restrict__ ridx1, const int* __restrict__ ridx2) {
    extern __shared__ float4 sdb[];        // NN entries, 64KB (w = 0.5*|p|^2)
    __shared__ uint2 scand[16][4][32];     // per-warp, per-query pending buf

    const int z = blockIdx.z;
    const int b = blockIdx.y;
    const int K = (z == 2) ? 32 : 16;
    const int slot_base = z * 16;          // 0, 16, 32
    const float* db = (z == 0) ? p1 : (z == 1) ? p2 : pc;

    const float* dbx = db + (long)b * 3 * NN;
    for (int j = threadIdx.x; j < NN; j += 512) {
        float x = dbx[j], y = dbx[NN + j], z2 = dbx[2 * NN + j];
        sdb[j] = make_float4(x, y, z2, 0.5f * fmaf(x, x, fmaf(y, y, z2 * z2)));
    }
    __syncthreads();

    const int w = threadIdx.x >> 5;
    const int lane = threadIdx.x & 31;
    const int qbase = blockIdx.x * 64 + w * 4;   // 4 consecutive queries/warp
    const unsigned lt = (1u << lane) - 1u;

    float qx[4], qy[4], qz[4];
#pragma unroll
    for (int q = 0; q < 4; q++) {
        int qi = qbase + q;
        if (qi < NQ1) {
            int idx = ridx1[b * NQ1 + qi];
            const float* s = p1 + (long)b * 3 * NN;
            qx[q] = -s[idx]; qy[q] = -s[NN + idx]; qz[q] = -s[2 * NN + idx];
        } else {
            int idx = ridx2[b * NQ2 + (qi - NQ1)];
            const float* s = p2 + (long)b * 3 * NN;
            qx[q] = -s[idx]; qy[q] = -s[NN + idx]; qz[q] = -s[2 * NN + idx];
        }
    }

    float s0[4], thr[4];
    int i0[4], pend[4];
    // Seed: per query, exact top-32 of batch 0 sorted across lanes.
    {
        float4 p = sdb[lane];
#pragma unroll
        for (int q = 0; q < 4; q++) {
            float s = fmaf(qx[q], p.x, fmaf(qy[q], p.y, fmaf(qz[q], p.z, p.w)));
            int i = lane;
            sort32(s, i, lane);
            s0[q] = s; i0[q] = i;
            thr[q] = __shfl_sync(0xffffffffu, s, K - 1);
            pend[q] = 0;
        }
    }

    for (int j0 = 32; j0 < NN; j0 += 32) {
        float4 p = sdb[j0 + lane];
        float sc[4];
#pragma unroll
        for (int q = 0; q < 4; q++)
            sc[q] = fmaf(qx[q], p.x, fmaf(qy[q], p.y, fmaf(qz[q], p.z, p.w)));
        unsigned m[4];
#pragma unroll
        for (int q = 0; q < 4; q++)
            m[q] = __ballot_sync(0xffffffffu, sc[q] < thr[q]);
        if (m[0] | m[1] | m[2] | m[3]) {           // warp-uniform
#pragma unroll
            for (int q = 0; q < 4; q++) {
                if (m[q]) {                         // warp-uniform
                    int n = __popc(m[q]);
                    if (pend[q] + n > 32) {
                        knn_flush(scand[w][q], lane, s0[q], i0[q], pend[q],
                                  thr[q], K);
                        m[q] = __ballot_sync(0xffffffffu, sc[q] < thr[q]);
                        n = __popc(m[q]);
                    }
                    if (sc[q] < thr[q]) {
                        scand[w][q][pend[q] + __popc(m[q] & lt)] =
                            make_uint2(__float_as_uint(sc[q]),
                                       (unsigned)(j0 + lane));
                    }
                    pend[q] += n;
                }
            }
        }
    }

#pragma unroll
    for (int q = 0; q < 4; q++) {
        if (pend[q])
            knn_flush(scand[w][q], lane, s0[q], i0[q], pend[q], thr[q], K);
        if (lane < K) {
            float4 p = sdb[i0[q]];
            float rx = p.x + qx[q], ry = p.y + qy[q], rz = p.z + qz[q];
            float sq = fmaf(rx, rx, fmaf(ry, ry, rz * rz));
            float dd = (sq > 0.f) ? sqrtf(sq) : 0.f;
            const long pt = (long)b * NN + qbase + q;
            g_feats[pt * KTOT + slot_base + lane] = make_float4(rx, ry, rz, dd);
            float* go = g_grouped + (pt * KTOT + slot_base + lane) * 3;
            go[0] = p.x;
            go[1] = p.y;
            go[2] = p.z;
        }
    }
}

// ---------------------------------------------------------------------------
// Attention + weighted fusion (rank-4 factorization).
// ---------------------------------------------------------------------------
__global__ __launch_bounds__(256) void attn_kernel(
    const float* __restrict__ Wv, const float* __restrict__ bv,
    float* __restrict__ out) {
    __shared__ float4 sF[4][64];
    __shared__ float  sB[4][64];
    __shared__ float  sS[4][64];
    __shared__ float  sWv[4][64];
    __shared__ float  sbv[64];
    __shared__ float  sRed[4][2][3];

    const int tid = threadIdx.x;
    const int g = tid >> 6;
    const int t = tid & 63;

    sWv[g][t] = Wv[tid];
    if (tid < 64) sbv[tid] = bv[tid];

    const long pt = (long)blockIdx.x * 4 + g;

    float4 F = g_feats[pt * KTOT + t];
    sF[g][t] = F;

    float P0 = F.x * g_G[0]  + F.y * g_G[4]  + F.z * g_G[8]  + F.w * g_G[12];
    float P1 = F.x * g_G[1]  + F.y * g_G[5]  + F.z * g_G[9]  + F.w * g_G[13];
    float P2 = F.x * g_G[2]  + F.y * g_G[6]  + F.z * g_G[10] + F.w * g_G[14];
    float P3 = F.x * g_G[3]  + F.y * g_G[7]  + F.z * g_G[11] + F.w * g_G[15];
    float a_t = F.x * g_u[0] + F.y * g_u[1] + F.z * g_u[2] + F.w * g_u[3] + g_c0;
    float b_t = F.x * g_w[0] + F.y * g_w[1] + F.z * g_w[2] + F.w * g_w[3];
    sB[g][t] = b_t;

    float gx = g_grouped[(pt * KTOT + t) * 3 + 0];
    float gy = g_grouped[(pt * KTOT + t) * 3 + 1];
    float gz = g_grouped[(pt * KTOT + t) * 3 + 2];

    __syncthreads();

    const float scale = 0.125f;

    float m = -FINF;
#pragma unroll 8
    for (int j = 0; j < 64; j++) {
        float4 Fj = sF[g][j];
        float l = fmaf(P0, Fj.x, fmaf(P1, Fj.y, fmaf(P2, Fj.z, fmaf(P3, Fj.w, a_t + sB[g][j])))) * scale;
        m = fmaxf(m, l);
    }

    float ssum = 0.f, a0 = 0.f, a1 = 0.f, a2 = 0.f, a3 = 0.f;
#pragma unroll 8
    for (int j = 0; j < 64; j++) {
        float4 Fj = sF[g][j];
        float l = fmaf(P0, Fj.x, fmaf(P1, Fj.y, fmaf(P2, Fj.z, fmaf(P3, Fj.w, a_t + sB[g][j])))) * scale;
        float e = __expf(l - m);
        ssum += e;
        a0 = fmaf(e, Fj.x, a0);
        a1 = fmaf(e, Fj.y, a1);
        a2 = fmaf(e, Fj.z, a2);
        a3 = fmaf(e, Fj.w, a3);
    }
    float inv = 1.f / ssum;
    a0 *= inv; a1 *= inv; a2 *= inv; a3 *= inv;

    float sc = -FINF;
#pragma unroll 8
    for (int c = 0; c < 64; c++) {
        float y = fmaf(a0, sWv[0][c], fmaf(a1, sWv[1][c], fmaf(a2, sWv[2][c], fmaf(a3, sWv[3][c], sbv[c]))));
        sc = fmaxf(sc, y);
    }
    sS[g][t] = sc;
    __syncthreads();

    float m2 = -FINF;
#pragma unroll 8
    for (int j = 0; j < 64; j++) m2 = fmaxf(m2, sS[g][j]);
    float e_t = __expf(sc - m2);
    sB[g][t] = e_t;
    __syncthreads();
    float sum2 = 0.f;
#pragma unroll 8
    for (int j = 0; j < 64; j++) sum2 += sB[g][j];
    float wgt = e_t / sum2;

    float cx = wgt * gx, cy = wgt * gy, cz = wgt * gz;
#pragma unroll
    for (int off = 16; off > 0; off >>= 1) {
        cx += __shfl_down_sync(0xffffffffu, cx, off);
        cy += __shfl_down_sync(0xffffffffu, cy, off);
        cz += __shfl_down_sync(0xffffffffu, cz, off);
    }
    const int wg = t >> 5;
    if ((t & 31) == 0) {
        sRed[g][wg][0] = cx; sRed[g][wg][1] = cy; sRed[g][wg][2] = cz;
    }
    __syncthreads();
    if (t == 0) {
        int b = (int)(pt / NN);
        int n = (int)(pt % NN);
        out[(long)b * 3 * NN + 0 * NN + n] = sRed[g][0][0] + sRed[g][1][0];
        out[(long)b * 3 * NN + 1 * NN + n] = sRed[g][0][1] + sRed[g][1][1];
        out[(long)b * 3 * NN + 2 * NN + n] = sRed[g][0][2] + sRed[g][1][2];
    }
}

// ---------------------------------------------------------------------------
extern "C" void kernel_launch(void* const* d_in, const int* in_sizes, int n_in,
                              void* d_out, int out_size) {
    const float* points1 = (const float*)d_in[0];
    const float* points2 = (const float*)d_in[1];
    const float* pc      = (const float*)d_in[2];
    const float* Wq      = (const float*)d_in[3];
    const float* Wk      = (const float*)d_in[4];
    const float* Wv      = (const float*)d_in[5];
    const float* bq      = (const float*)d_in[6];
    const float* bk      = (const float*)d_in[7];
    const float* bv      = (const float*)d_in[8];
    const int*   ridx1   = (const int*)d_in[9];
    const int*   ridx2   = (const int*)d_in[10];
    float* out = (float*)d_out;

    const size_t smem = (size_t)NN * sizeof(float4);  // 64KB dynamic
    cudaFuncSetAttribute(knn_kernel, cudaFuncAttributeMaxDynamicSharedMemorySize, (int)smem);

    precompute_kernel<<<1, 64>>>(Wq, Wk, bq, bk);

    // 64 query-chunks (64 queries each) x 8 batches x 3 knn types
    dim3 grid(NN / 64, BB, 3);
    knn_kernel<<<grid, 512, smem>>>(points1, points2, pc, ridx1, ridx2);

    attn_kernel<<<(BB * NN) / 4, 256>>>(Wv, bv, out);
}